// round 10
// baseline (speedup 1.0000x reference)
#include <cuda_runtime.h>
#include <math.h>

#define SLOPE 0.2f
#define NB   32
#define TT   1002
#define DD   16
#define EE   32
#define HH   64
#define LEN  1000
#define NN   (NB*LEN)
#define TPB  256
#define STILE 64          // samples per CTA

#define RS_A 68           // activation row stride (floats)
#define RS_W 68           // transposed-weight row stride

// smem layout offsets (floats)
#define OFF_IT   0                         // It  : 33 * 68 = 2244
#define OFF_W0T  2244                      // W0t : 33 * 68 = 2244
#define OFF_W1T  4488                      // W1t : 64 * 68 = 4352
#define OFF_W2T  8840                      // W2t : 64 * 68 = 4352
#define OFF_B0   13192                     // B0  : 64 * 68 = 4352
#define OFF_B1   17544                     // B1  : 64 * 68 = 4352
#define OFF_SB0  21896
#define OFF_SB1  21960
#define OFF_SB2  22024
#define OFF_WO   22088
#define OFF_BO   22152
#define SMEM_FLOATS 22156
#define SMEM_BYTES  (SMEM_FLOATS * 4)      // 88624 B -> 2 CTAs/SM

// scratch for per-(n,d) log|dJ|
__device__ float g_logscratch[NN * DD];

// ---- packed f32x2 helpers (sm_100+) ----
static __device__ __forceinline__ unsigned long long pack2(float v) {
    unsigned long long r;
    unsigned u = __float_as_uint(v);
    asm("mov.b64 %0, {%1, %1};" : "=l"(r) : "r"(u));
    return r;
}
static __device__ __forceinline__ void fma2(unsigned long long& d,
                                            unsigned long long a,
                                            unsigned long long b) {
    asm("fma.rn.f32x2 %0, %1, %2, %0;" : "+l"(d) : "l"(a), "l"(b));
}
static __device__ __forceinline__ void unpack2(unsigned long long v, float& lo, float& hi) {
    unsigned ulo, uhi;
    asm("mov.b64 {%0, %1}, %2;" : "=r"(ulo), "=r"(uhi) : "l"(v));
    lo = __uint_as_float(ulo);
    hi = __uint_as_float(uhi);
}

// acc[k][m] += Wt[j][o0+k] * Ain[j][s0+2m..2m+1], k<2, m<4
static __device__ __forceinline__ void gemv_tile_f2(
    const float* __restrict__ Wt, const float* __restrict__ Ain,
    int nj, int o0, int s0, unsigned long long acc[2][4])
{
    #pragma unroll 8
    for (int j = 0; j < nj; j++) {
        const float2 wv = *reinterpret_cast<const float2*>(&Wt[j * RS_W + o0]);
        const ulonglong2 p0 = *reinterpret_cast<const ulonglong2*>(&Ain[j * RS_A + s0]);
        const ulonglong2 p1 = *reinterpret_cast<const ulonglong2*>(&Ain[j * RS_A + s0 + 4]);
        unsigned long long am[4] = {p0.x, p0.y, p1.x, p1.y};
        unsigned long long w0 = pack2(wv.x);
        unsigned long long w1 = pack2(wv.y);
        #pragma unroll
        for (int m = 0; m < 4; m++) fma2(acc[0][m], w0, am[m]);
        #pragma unroll
        for (int m = 0; m < 4; m++) fma2(acc[1][m], w1, am[m]);
    }
}

static __device__ __forceinline__ void zero_acc(unsigned long long acc[2][4]) {
    #pragma unroll
    for (int k = 0; k < 2; k++)
        #pragma unroll
        for (int m = 0; m < 4; m++) acc[k][m] = 0ull;
}

__global__ __launch_bounds__(TPB, 2)
void mlp_fused_kernel(
    const float* __restrict__ x,   const float* __restrict__ emb,
    const float* __restrict__ W0,  const float* __restrict__ b0,
    const float* __restrict__ W1,  const float* __restrict__ b1,
    const float* __restrict__ W2,  const float* __restrict__ b2,
    const float* __restrict__ Wo,  const float* __restrict__ bo,
    float* __restrict__ out_res)
{
    extern __shared__ float sm[];
    float* It  = sm + OFF_IT;
    float* W0t = sm + OFF_W0T;
    float* W1t = sm + OFF_W1T;
    float* W2t = sm + OFF_W2T;
    float* B0  = sm + OFF_B0;
    float* B1  = sm + OFF_B1;
    float* sb0 = sm + OFF_SB0;
    float* sb1 = sm + OFF_SB1;
    float* sb2 = sm + OFF_SB2;
    float* sWo = sm + OFF_WO;

    const int d   = blockIdx.y;
    const int tid = threadIdx.x;
    const int n0  = blockIdx.x * STILE;

    // ---- stage W0 transposed: W0t[e][h] = W0[d][h][e] ----
    for (int idx = tid; idx < HH * (EE + 1); idx += TPB) {
        int h = idx / (EE + 1), e = idx - h * (EE + 1);
        W0t[e * RS_W + h] = W0[(d * HH + h) * (EE + 1) + e];
    }
    // ---- stage W1, W2 transposed ----
    {
        const float4* w1g = reinterpret_cast<const float4*>(W1 + d * HH * HH);
        const float4* w2g = reinterpret_cast<const float4*>(W2 + d * HH * HH);
        for (int idx = tid; idx < HH * (HH / 4); idx += TPB) {
            int o = idx >> 4, j4 = idx & 15;
            float4 w = w1g[o * 16 + j4];
            W1t[(4*j4+0) * RS_W + o] = w.x;
            W1t[(4*j4+1) * RS_W + o] = w.y;
            W1t[(4*j4+2) * RS_W + o] = w.z;
            W1t[(4*j4+3) * RS_W + o] = w.w;
            w = w2g[o * 16 + j4];
            W2t[(4*j4+0) * RS_W + o] = w.x;
            W2t[(4*j4+1) * RS_W + o] = w.y;
            W2t[(4*j4+2) * RS_W + o] = w.z;
            W2t[(4*j4+3) * RS_W + o] = w.w;
        }
    }
    for (int i = tid; i < HH; i += TPB) {
        sb0[i] = b0[d * HH + i];
        sb1[i] = b1[d * HH + i];
        sb2[i] = b2[d * HH + i];
        sWo[i] = Wo[d * HH + i];
    }
    if (tid == 0) sm[OFF_BO] = bo[d];

    // ---- stage inputs transposed: It[e][s] = emb[row(s)][e]; It[32][s] = x_t ----
    for (int idx = tid; idx < STILE * EE; idx += TPB) {
        int s = idx >> 5, e = idx & 31;
        int n = n0 + s, b = n / LEN, t = n - b * LEN;
        int row = b * TT + t + 2;                 // LAGS = 2
        It[e * RS_A + s] = emb[(size_t)row * EE + e];
    }
    if (tid < STILE) {
        int n = n0 + tid, b = n / LEN, t = n - b * LEN;
        int row = b * TT + t + 2;
        It[EE * RS_A + tid] = x[(size_t)row * DD + d];
    }
    __syncthreads();

    const int o0 = (tid >> 3) * 2;    // 0..62, 2 outputs per thread
    const int s0 = (tid & 7) * 8;     // 0..56, 8 samples per thread

    unsigned long long acc[2][4];
    unsigned g0b = 0, g1b = 0, g2b = 0;   // 16 gate bits per layer, thread-local

    // ================= forward =================
    // layer 0 (33 input rows): It -> B1
    zero_acc(acc);
    gemv_tile_f2(W0t, It, EE + 1, o0, s0, acc);
    #pragma unroll
    for (int k = 0; k < 2; k++) {
        float bb = sb0[o0 + k];
        #pragma unroll
        for (int m = 0; m < 4; m++) {
            float lo, hi; unpack2(acc[k][m], lo, hi);
            float z0 = lo + bb, z1 = hi + bb;
            unsigned p0 = (z0 >= 0.f), p1 = (z1 >= 0.f);
            g0b |= (p0 | (p1 << 1)) << (k*8 + m*2);
            B1[(o0 + k) * RS_A + s0 + 2*m + 0] = p0 ? z0 : z0 * SLOPE;
            B1[(o0 + k) * RS_A + s0 + 2*m + 1] = p1 ? z1 : z1 * SLOPE;
        }
    }
    __syncthreads();

    // layer 1: B1 -> B0
    zero_acc(acc);
    gemv_tile_f2(W1t, B1, HH, o0, s0, acc);
    #pragma unroll
    for (int k = 0; k < 2; k++) {
        float bb = sb1[o0 + k];
        #pragma unroll
        for (int m = 0; m < 4; m++) {
            float lo, hi; unpack2(acc[k][m], lo, hi);
            float z0 = lo + bb, z1 = hi + bb;
            unsigned p0 = (z0 >= 0.f), p1 = (z1 >= 0.f);
            g1b |= (p0 | (p1 << 1)) << (k*8 + m*2);
            B0[(o0 + k) * RS_A + s0 + 2*m + 0] = p0 ? z0 : z0 * SLOPE;
            B0[(o0 + k) * RS_A + s0 + 2*m + 1] = p1 ? z1 : z1 * SLOPE;
        }
    }
    __syncthreads();

    // layer 2: B0 -> B1
    zero_acc(acc);
    gemv_tile_f2(W2t, B0, HH, o0, s0, acc);
    #pragma unroll
    for (int k = 0; k < 2; k++) {
        float bb = sb2[o0 + k];
        #pragma unroll
        for (int m = 0; m < 4; m++) {
            float lo, hi; unpack2(acc[k][m], lo, hi);
            float z0 = lo + bb, z1 = hi + bb;
            unsigned p0 = (z0 >= 0.f), p1 = (z1 >= 0.f);
            g2b |= (p0 | (p1 << 1)) << (k*8 + m*2);
            B1[(o0 + k) * RS_A + s0 + 2*m + 0] = p0 ? z0 : z0 * SLOPE;
            B1[(o0 + k) * RS_A + s0 + 2*m + 1] = p1 ? z1 : z1 * SLOPE;
        }
    }
    __syncthreads();

    // ---- residual head (reads B1 = a2) + tangent seed t0 -> B0 ----
    if (tid < STILE) {
        float r = sm[OFF_BO];
        #pragma unroll 8
        for (int h = 0; h < HH; h++) r += sWo[h] * B1[h * RS_A + tid];
        int n = n0 + tid;
        out_res[(size_t)n * DD + d] = r;
    }
    #pragma unroll
    for (int k = 0; k < 2; k++) {
        float wE = W0t[EE * RS_W + o0 + k];      // W0[:, E] for this output row
        #pragma unroll
        for (int m = 0; m < 4; m++) {
            unsigned b2b = (g0b >> (k*8 + m*2)) & 3u;
            B0[(o0 + k) * RS_A + s0 + 2*m + 0] = ((b2b & 1u) ? 1.f : SLOPE) * wE;
            B0[(o0 + k) * RS_A + s0 + 2*m + 1] = ((b2b & 2u) ? 1.f : SLOPE) * wE;
        }
    }
    __syncthreads();

    // t1 = g1 * (W1 @ t0): B0 -> B1
    zero_acc(acc);
    gemv_tile_f2(W1t, B0, HH, o0, s0, acc);
    #pragma unroll
    for (int k = 0; k < 2; k++)
        #pragma unroll
        for (int m = 0; m < 4; m++) {
            float lo, hi; unpack2(acc[k][m], lo, hi);
            unsigned b2b = (g1b >> (k*8 + m*2)) & 3u;
            B1[(o0 + k) * RS_A + s0 + 2*m + 0] = ((b2b & 1u) ? 1.f : SLOPE) * lo;
            B1[(o0 + k) * RS_A + s0 + 2*m + 1] = ((b2b & 2u) ? 1.f : SLOPE) * hi;
        }
    __syncthreads();

    // t2 = g2 * (W2 @ t1): B1 -> B0
    zero_acc(acc);
    gemv_tile_f2(W2t, B1, HH, o0, s0, acc);
    #pragma unroll
    for (int k = 0; k < 2; k++)
        #pragma unroll
        for (int m = 0; m < 4; m++) {
            float lo, hi; unpack2(acc[k][m], lo, hi);
            unsigned b2b = (g2b >> (k*8 + m*2)) & 3u;
            B0[(o0 + k) * RS_A + s0 + 2*m + 0] = ((b2b & 1u) ? 1.f : SLOPE) * lo;
            B0[(o0 + k) * RS_A + s0 + 2*m + 1] = ((b2b & 2u) ? 1.f : SLOPE) * hi;
        }
    __syncthreads();

    // ---- Jacobian head (reads B0 = t2) ----
    if (tid < STILE) {
        float dJ = 0.f;
        #pragma unroll 8
        for (int h = 0; h < HH; h++) dJ += sWo[h] * B0[h * RS_A + tid];
        int n = n0 + tid;
        g_logscratch[(size_t)n * DD + d] = logf(fabsf(dJ));
    }
}

// deterministic fixed-order reduction over d for log|det J|
__global__ void logdet_reduce_kernel(float* __restrict__ out_log)
{
    int n = blockIdx.x * 256 + threadIdx.x;
    if (n >= NN) return;
    const float4* p = reinterpret_cast<const float4*>(&g_logscratch[(size_t)n * DD]);
    float s = 0.f;
    #pragma unroll
    for (int i = 0; i < DD / 4; i++) {
        float4 v4 = p[i];
        s += v4.x; s += v4.y; s += v4.z; s += v4.w;
    }
    out_log[n] = s;
}

extern "C" void kernel_launch(void* const* d_in, const int* in_sizes, int n_in,
                              void* d_out, int out_size)
{
    const float* x   = (const float*)d_in[0];
    const float* emb = (const float*)d_in[1];
    const float* W0  = (const float*)d_in[2];
    const float* b0  = (const float*)d_in[3];
    const float* W1  = (const float*)d_in[4];
    const float* b1  = (const float*)d_in[5];
    const float* W2  = (const float*)d_in[6];
    const float* b2  = (const float*)d_in[7];
    const float* Wo  = (const float*)d_in[8];
    const float* bo  = (const float*)d_in[9];

    float* out_res = (float*)d_out;            // [N, D]
    float* out_log = (float*)d_out + NN * DD;  // [N]

    cudaFuncSetAttribute(mlp_fused_kernel,
                         cudaFuncAttributeMaxDynamicSharedMemorySize, SMEM_BYTES);

    dim3 grid(NN / STILE, DD);   // 500 x 16
    mlp_fused_kernel<<<grid, TPB, SMEM_BYTES>>>(x, emb, W0, b0, W1, b1, W2, b2, Wo, bo, out_res);
    logdet_reduce_kernel<<<(NN + 255) / 256, 256>>>(out_log);
}

// round 11
// speedup vs baseline: 1.3427x; 1.3427x over previous
#include <cuda_runtime.h>
#include <math.h>

#define SLOPE 0.2f
#define NB   32
#define TT   1002
#define DD   16
#define EE   32
#define HH   64
#define LEN  1000
#define NN   (NB*LEN)
#define TPB  128
#define STILE 64          // samples per CTA

#define RS_A 68           // activation row stride (floats): 64 + 4 pad, 16B-aligned rows
#define RS_W 68           // transposed-weight row stride

// smem layout offsets (floats)
#define OFF_IT   0                         // It  : 33 * 68 = 2244
#define OFF_W0T  2244                      // W0t : 33 * 68 = 2244
#define OFF_W1T  4488                      // W1t : 64 * 68 = 4352
#define OFF_W2T  8840                      // W2t : 64 * 68 = 4352
#define OFF_A0   13192                     // A0  : 64 * 68 = 4352
#define OFF_A1   17544
#define OFF_A2   21896
#define OFF_B0   26248
#define OFF_B1   26312
#define OFF_B2   26376
#define OFF_WO   26440
#define OFF_BO   26504
#define SMEM_FLOATS 26508
#define SMEM_BYTES  (SMEM_FLOATS * 4)

// scratch for per-(n,d) log|dJ|
__device__ float g_logscratch[NN * DD];

// ---- packed f32x2 helpers (sm_100+) ----
static __device__ __forceinline__ unsigned long long pack2(float v) {
    unsigned long long r;
    unsigned u = __float_as_uint(v);
    asm("mov.b64 %0, {%1, %1};" : "=l"(r) : "r"(u));
    return r;
}
static __device__ __forceinline__ void fma2(unsigned long long& d,
                                            unsigned long long a,
                                            unsigned long long b) {
    asm("fma.rn.f32x2 %0, %1, %2, %0;" : "+l"(d) : "l"(a), "l"(b));
}
static __device__ __forceinline__ void unpack2(unsigned long long v, float& lo, float& hi) {
    unsigned ulo, uhi;
    asm("mov.b64 {%0, %1}, %2;" : "=r"(ulo), "=r"(uhi) : "l"(v));
    lo = __uint_as_float(ulo);
    hi = __uint_as_float(uhi);
}

// acc[k][m] += Wt[j][o0+k] * Ain[j][s0 + 2m .. 2m+1]  (packed pairs), j = 0..nj-1
static __device__ __forceinline__ void gemv_tile_f2(
    const float* __restrict__ Wt, const float* __restrict__ Ain,
    int nj, int o0, int s0, unsigned long long acc[4][4])
{
    #pragma unroll 8
    for (int j = 0; j < nj; j++) {
        const float4 wv = *reinterpret_cast<const float4*>(&Wt[j * RS_W + o0]);
        const ulonglong2 p0 = *reinterpret_cast<const ulonglong2*>(&Ain[j * RS_A + s0]);
        const ulonglong2 p1 = *reinterpret_cast<const ulonglong2*>(&Ain[j * RS_A + s0 + 4]);
        unsigned long long am[4] = {p0.x, p0.y, p1.x, p1.y};
        unsigned long long wk[4] = {pack2(wv.x), pack2(wv.y), pack2(wv.z), pack2(wv.w)};
        #pragma unroll
        for (int k = 0; k < 4; k++)
            #pragma unroll
            for (int m = 0; m < 4; m++)
                fma2(acc[k][m], wk[k], am[m]);
    }
}

static __device__ __forceinline__ void zero_acc(unsigned long long acc[4][4]) {
    #pragma unroll
    for (int k = 0; k < 4; k++)
        #pragma unroll
        for (int m = 0; m < 4; m++) acc[k][m] = 0ull;
}

// no-op spacer: shifts launch indices so ncu (-s 5 -c 1) captures the MAIN kernel
__global__ void nop_kernel() {}

__global__ __launch_bounds__(TPB, 2)
void mlp_fused_kernel(
    const float* __restrict__ x,   const float* __restrict__ emb,
    const float* __restrict__ W0,  const float* __restrict__ b0,
    const float* __restrict__ W1,  const float* __restrict__ b1,
    const float* __restrict__ W2,  const float* __restrict__ b2,
    const float* __restrict__ Wo,  const float* __restrict__ bo,
    float* __restrict__ out_res)
{
    extern __shared__ float sm[];
    float* It  = sm + OFF_IT;
    float* W0t = sm + OFF_W0T;
    float* W1t = sm + OFF_W1T;
    float* W2t = sm + OFF_W2T;
    float* A0  = sm + OFF_A0;
    float* A1  = sm + OFF_A1;
    float* A2  = sm + OFF_A2;
    float* sb0 = sm + OFF_B0;
    float* sb1 = sm + OFF_B1;
    float* sb2 = sm + OFF_B2;
    float* sWo = sm + OFF_WO;

    const int d   = blockIdx.y;
    const int tid = threadIdx.x;
    const int n0  = blockIdx.x * STILE;

    // ---- stage W0 transposed: W0t[e][h] = W0[d][h][e] ----
    for (int idx = tid; idx < HH * (EE + 1); idx += TPB) {
        int h = idx / (EE + 1), e = idx - h * (EE + 1);
        W0t[e * RS_W + h] = W0[(d * HH + h) * (EE + 1) + e];
    }
    // ---- stage W1, W2 transposed ----
    {
        const float4* w1g = reinterpret_cast<const float4*>(W1 + d * HH * HH);
        const float4* w2g = reinterpret_cast<const float4*>(W2 + d * HH * HH);
        for (int idx = tid; idx < HH * (HH / 4); idx += TPB) {
            int o = idx >> 4, j4 = idx & 15;
            float4 w = w1g[o * 16 + j4];
            W1t[(4*j4+0) * RS_W + o] = w.x;
            W1t[(4*j4+1) * RS_W + o] = w.y;
            W1t[(4*j4+2) * RS_W + o] = w.z;
            W1t[(4*j4+3) * RS_W + o] = w.w;
            w = w2g[o * 16 + j4];
            W2t[(4*j4+0) * RS_W + o] = w.x;
            W2t[(4*j4+1) * RS_W + o] = w.y;
            W2t[(4*j4+2) * RS_W + o] = w.z;
            W2t[(4*j4+3) * RS_W + o] = w.w;
        }
    }
    for (int i = tid; i < HH; i += TPB) {
        sb0[i] = b0[d * HH + i];
        sb1[i] = b1[d * HH + i];
        sb2[i] = b2[d * HH + i];
        sWo[i] = Wo[d * HH + i];
    }
    if (tid == 0) sm[OFF_BO] = bo[d];

    // ---- stage inputs transposed: It[e][s] = emb[row(s)][e]; It[32][s] = x_t ----
    for (int idx = tid; idx < STILE * EE; idx += TPB) {
        int s = idx >> 5, e = idx & 31;
        int n = n0 + s, b = n / LEN, t = n - b * LEN;
        int row = b * TT + t + 2;                 // LAGS = 2
        It[e * RS_A + s] = emb[(size_t)row * EE + e];
    }
    if (tid < STILE) {
        int n = n0 + tid, b = n / LEN, t = n - b * LEN;
        int row = b * TT + t + 2;
        It[EE * RS_A + tid] = x[(size_t)row * DD + d];
    }
    __syncthreads();

    const int o0 = (tid >> 3) * 4;    // 0..60
    const int s0 = (tid & 7) * 8;     // 0..56

    unsigned long long acc[4][4];

    // ================= forward =================
    // layer 0 (33 input rows)
    zero_acc(acc);
    gemv_tile_f2(W0t, It, EE + 1, o0, s0, acc);
    #pragma unroll
    for (int k = 0; k < 4; k++) {
        float bb = sb0[o0 + k];
        #pragma unroll
        for (int m = 0; m < 4; m++) {
            float lo, hi; unpack2(acc[k][m], lo, hi);
            float z0 = lo + bb, z1 = hi + bb;
            A0[(o0 + k) * RS_A + s0 + 2*m + 0] = (z0 >= 0.f) ? z0 : z0 * SLOPE;
            A0[(o0 + k) * RS_A + s0 + 2*m + 1] = (z1 >= 0.f) ? z1 : z1 * SLOPE;
        }
    }
    __syncthreads();

    // layer 1
    zero_acc(acc);
    gemv_tile_f2(W1t, A0, HH, o0, s0, acc);
    #pragma unroll
    for (int k = 0; k < 4; k++) {
        float bb = sb1[o0 + k];
        #pragma unroll
        for (int m = 0; m < 4; m++) {
            float lo, hi; unpack2(acc[k][m], lo, hi);
            float z0 = lo + bb, z1 = hi + bb;
            A1[(o0 + k) * RS_A + s0 + 2*m + 0] = (z0 >= 0.f) ? z0 : z0 * SLOPE;
            A1[(o0 + k) * RS_A + s0 + 2*m + 1] = (z1 >= 0.f) ? z1 : z1 * SLOPE;
        }
    }
    __syncthreads();

    // layer 2
    zero_acc(acc);
    gemv_tile_f2(W2t, A1, HH, o0, s0, acc);
    #pragma unroll
    for (int k = 0; k < 4; k++) {
        float bb = sb2[o0 + k];
        #pragma unroll
        for (int m = 0; m < 4; m++) {
            float lo, hi; unpack2(acc[k][m], lo, hi);
            float z0 = lo + bb, z1 = hi + bb;
            A2[(o0 + k) * RS_A + s0 + 2*m + 0] = (z0 >= 0.f) ? z0 : z0 * SLOPE;
            A2[(o0 + k) * RS_A + s0 + 2*m + 1] = (z1 >= 0.f) ? z1 : z1 * SLOPE;
        }
    }
    __syncthreads();

    // ---- residual head + tangent seed t0 (in place on A0) ----
    // gate reconstructible from sign: a = z*g with g>0 => (a>=0) <=> (z>=0)
    if (tid < STILE) {
        float r = sm[OFF_BO];
        #pragma unroll 8
        for (int h = 0; h < HH; h++) r += sWo[h] * A2[h * RS_A + tid];
        int n = n0 + tid;
        out_res[(size_t)n * DD + d] = r;
    }
    for (int idx = tid; idx < HH * STILE; idx += TPB) {
        int o = idx >> 6, s = idx & 63;
        float a = A0[o * RS_A + s];
        float g = (a >= 0.f) ? 1.f : SLOPE;
        A0[o * RS_A + s] = g * W0t[EE * RS_W + o];   // g0 * W0[:, E]
    }
    __syncthreads();

    // t1 = g1 * (W1 @ t0), in place over A1
    zero_acc(acc);
    gemv_tile_f2(W1t, A0, HH, o0, s0, acc);
    #pragma unroll
    for (int k = 0; k < 4; k++)
        #pragma unroll
        for (int m = 0; m < 4; m++) {
            float lo, hi; unpack2(acc[k][m], lo, hi);
            float* p = &A1[(o0 + k) * RS_A + s0 + 2*m];
            float g0 = (p[0] >= 0.f) ? 1.f : SLOPE;
            float g1 = (p[1] >= 0.f) ? 1.f : SLOPE;
            p[0] = g0 * lo;
            p[1] = g1 * hi;
        }
    __syncthreads();

    // t2 = g2 * (W2 @ t1), in place over A2
    zero_acc(acc);
    gemv_tile_f2(W2t, A1, HH, o0, s0, acc);
    #pragma unroll
    for (int k = 0; k < 4; k++)
        #pragma unroll
        for (int m = 0; m < 4; m++) {
            float lo, hi; unpack2(acc[k][m], lo, hi);
            float* p = &A2[(o0 + k) * RS_A + s0 + 2*m];
            float g0 = (p[0] >= 0.f) ? 1.f : SLOPE;
            float g1 = (p[1] >= 0.f) ? 1.f : SLOPE;
            p[0] = g0 * lo;
            p[1] = g1 * hi;
        }
    __syncthreads();

    // ---- Jacobian head ----
    if (tid < STILE) {
        float dJ = 0.f;
        #pragma unroll 8
        for (int h = 0; h < HH; h++) dJ += sWo[h] * A2[h * RS_A + tid];
        int n = n0 + tid;
        g_logscratch[(size_t)n * DD + d] = logf(fabsf(dJ));
    }
}

// deterministic fixed-order reduction over d for log|det J|
__global__ void logdet_reduce_kernel(float* __restrict__ out_log)
{
    int n = blockIdx.x * 256 + threadIdx.x;
    if (n >= NN) return;
    const float4* p = reinterpret_cast<const float4*>(&g_logscratch[(size_t)n * DD]);
    float s = 0.f;
    #pragma unroll
    for (int i = 0; i < DD / 4; i++) {
        float4 v4 = p[i];
        s += v4.x; s += v4.y; s += v4.z; s += v4.w;
    }
    out_log[n] = s;
}

extern "C" void kernel_launch(void* const* d_in, const int* in_sizes, int n_in,
                              void* d_out, int out_size)
{
    const float* x   = (const float*)d_in[0];
    const float* emb = (const float*)d_in[1];
    const float* W0  = (const float*)d_in[2];
    const float* b0  = (const float*)d_in[3];
    const float* W1  = (const float*)d_in[4];
    const float* b1  = (const float*)d_in[5];
    const float* W2  = (const float*)d_in[6];
    const float* b2  = (const float*)d_in[7];
    const float* Wo  = (const float*)d_in[8];
    const float* bo  = (const float*)d_in[9];

    float* out_res = (float*)d_out;            // [N, D]
    float* out_log = (float*)d_out + NN * DD;  // [N]

    cudaFuncSetAttribute(mlp_fused_kernel,
                         cudaFuncAttributeMaxDynamicSharedMemorySize, SMEM_BYTES);

    // Launch pattern [nop, mlp, nop, reduce]: with ncu -s 5 -c 1, the 6th
    // launch (= 2nd call's mlp) is captured -> profile shows the MAIN kernel.
    nop_kernel<<<1, 32>>>();
    dim3 grid(NN / STILE, DD);   // 500 x 16
    mlp_fused_kernel<<<grid, TPB, SMEM_BYTES>>>(x, emb, W0, b0, W1, b1, W2, b2, Wo, bo, out_res);
    nop_kernel<<<1, 32>>>();
    logdet_reduce_kernel<<<(NN + 255) / 256, 256>>>(out_log);
}

// round 14
// speedup vs baseline: 2.0416x; 1.5205x over previous
#include <cuda_runtime.h>
#include <math.h>
#include <stdint.h>

#define SLOPE 0.2f
#define NB   32
#define TT   1002
#define DD   16
#define EE   32
#define HH   64
#define LEN  1000
#define NN   (NB*LEN)
#define TPB  128
#define MTILE 128

#define RSA   68      // A row stride (floats): 68 % 32 == 4 -> conflict-free frags
#define RSW   68      // W1/W2 row stride
#define RSW0  44      // W0 row stride: 44 % 32 == 12 -> conflict-free

// ---- smem float offsets ----
#define OFF_AHI  0                    // 128*68 = 8704
#define OFF_ALO  8704                 // 8704
#define OFF_W0H  17408                // 64*44 = 2816
#define OFF_W0L  20224
#define OFF_W1H  23040                // 64*68 = 4352
#define OFF_W1L  27392
#define OFF_W2H  31744
#define OFF_W2L  36096
#define MF_B0    40448
#define MF_B1    40512
#define MF_B2    40576
#define MF_WO    40640
#define MF_W0E   40704
#define MF_BO    40768
#define SMEM_FLOATS 40772
#define SMEM_BYTES  (SMEM_FLOATS * 4)   // 163088

__device__ float g_logscratch[NN * DD];

static __device__ __forceinline__ void tf32_split(float x, uint32_t& hi, uint32_t& lo) {
    uint32_t h;
    asm("cvt.rna.tf32.f32 %0, %1;" : "=r"(h) : "f"(x));
    float rem = x - __uint_as_float(h);
    uint32_t l;
    asm("cvt.rna.tf32.f32 %0, %1;" : "=r"(l) : "f"(rem));
    hi = h; lo = l;
}

// D += A(16x8) * B(8x8), tf32 inputs, f32 accumulate
static __device__ __forceinline__ void mma8(float c[4], const uint32_t a[4], const uint32_t b[2]) {
    asm volatile(
        "mma.sync.aligned.m16n8k8.row.col.f32.tf32.tf32.f32 "
        "{%0,%1,%2,%3},{%4,%5,%6,%7},{%8,%9},{%0,%1,%2,%3};"
        : "+f"(c[0]), "+f"(c[1]), "+f"(c[2]), "+f"(c[3])
        : "r"(a[0]), "r"(a[1]), "r"(a[2]), "r"(a[3]), "r"(b[0]), "r"(b[1]));
}

// one 3xTF32 GEMM round: acc[2][8][4] += A[warp rows x 8*NK] * W^T
template<int NK, int RSWB>
static __device__ __forceinline__ void mma_round(
    const uint32_t* __restrict__ smu, int bh_off, int bl_off,
    int lane, int wrow, float acc[2][8][4])
{
    #pragma unroll
    for (int m = 0; m < 2; m++)
        #pragma unroll
        for (int n = 0; n < 8; n++)
            #pragma unroll
            for (int q = 0; q < 4; q++) acc[m][n][q] = 0.f;

    const int r0 = lane >> 2, c0 = lane & 3;
    #pragma unroll 2
    for (int k = 0; k < NK; k++) {
        uint32_t ah[2][4], al[2][4];
        #pragma unroll
        for (int m = 0; m < 2; m++)
            #pragma unroll
            for (int q = 0; q < 4; q++) {
                int idx = (wrow + m*16 + r0 + ((q & 1) << 3)) * RSA
                        + k*8 + c0 + ((q >> 1) << 2);
                ah[m][q] = smu[OFF_AHI + idx];
                al[m][q] = smu[OFF_ALO + idx];
            }
        uint32_t bh[8][2], bl[8][2];
        #pragma unroll
        for (int n = 0; n < 8; n++) {
            int idx = (n*8 + r0) * RSWB + k*8 + c0;
            bh[n][0] = smu[bh_off + idx];
            bh[n][1] = smu[bh_off + idx + 4];
            bl[n][0] = smu[bl_off + idx];
            bl[n][1] = smu[bl_off + idx + 4];
        }
        #pragma unroll
        for (int n = 0; n < 8; n++)
            #pragma unroll
            for (int m = 0; m < 2; m++) mma8(acc[m][n], ah[m], bh[n]);
        #pragma unroll
        for (int n = 0; n < 8; n++)
            #pragma unroll
            for (int m = 0; m < 2; m++) mma8(acc[m][n], ah[m], bl[n]);
        #pragma unroll
        for (int n = 0; n < 8; n++)
            #pragma unroll
            for (int m = 0; m < 2; m++) mma8(acc[m][n], al[m], bh[n]);
    }
}

__global__ __launch_bounds__(TPB)
void mlp_hmma_kernel(
    const float* __restrict__ x,   const float* __restrict__ emb,
    const float* __restrict__ W0,  const float* __restrict__ b0,
    const float* __restrict__ W1,  const float* __restrict__ b1,
    const float* __restrict__ W2,  const float* __restrict__ b2,
    const float* __restrict__ Wo,  const float* __restrict__ bo,
    float* __restrict__ out_res)
{
    extern __shared__ __align__(16) float sm[];
    uint32_t* smu = (uint32_t*)sm;

    const int d    = blockIdx.y;
    const int tid  = threadIdx.x;
    const int lane = tid & 31;
    const int wid  = tid >> 5;
    const int n0   = blockIdx.x * MTILE;
    const int wrow = wid * 32;

    // ================= staging =================
    {
        const float* w0g = W0 + (size_t)d * HH * (EE + 1);
        const float* w1g = W1 + (size_t)d * HH * HH;
        const float* w2g = W2 + (size_t)d * HH * HH;
        for (int idx = tid; idx < HH * HH; idx += TPB) {
            int o = idx >> 6, j = idx & 63;
            uint32_t h, l;
            tf32_split(w1g[idx], h, l);
            smu[OFF_W1H + o*RSW + j] = h;
            smu[OFF_W1L + o*RSW + j] = l;
            tf32_split(w2g[idx], h, l);
            smu[OFF_W2H + o*RSW + j] = h;
            smu[OFF_W2L + o*RSW + j] = l;
        }
        for (int idx = tid; idx < HH * 33; idx += TPB) {
            int o = idx / 33, j = idx - o * 33;
            uint32_t h, l;
            tf32_split(w0g[o * 33 + j], h, l);
            smu[OFF_W0H + o*RSW0 + j] = h;
            smu[OFF_W0L + o*RSW0 + j] = l;
        }
        for (int idx = tid; idx < HH * 11; idx += TPB) {   // zero W0 cols 33..43
            int o = idx / 11, j = 33 + idx - o * 11;
            smu[OFF_W0H + o*RSW0 + j] = 0u;
            smu[OFF_W0L + o*RSW0 + j] = 0u;
        }
        if (tid < HH) {
            sm[MF_B0  + tid] = b0[d * HH + tid];
            sm[MF_B1  + tid] = b1[d * HH + tid];
            sm[MF_B2  + tid] = b2[d * HH + tid];
            sm[MF_WO  + tid] = Wo[d * HH + tid];
            sm[MF_W0E + tid] = w0g[tid * 33 + 32];
        }
        if (tid == 0) sm[MF_BO] = bo[d];

        // inputs: row=tid; cols 0..31 = emb(tf32 split), col 32 = x_t, 33..39 = 0
        int n = n0 + tid, bb = n / LEN;
        int row = bb * TT + (n - bb * LEN) + 2;        // LAGS = 2
        const float4* ev = (const float4*)(emb + (size_t)row * EE);
        #pragma unroll
        for (int q8 = 0; q8 < 8; q8++) {
            float4 v = ev[q8];
            uint32_t h, l;
            tf32_split(v.x, h, l);
            smu[OFF_AHI + tid*RSA + q8*4+0] = h; smu[OFF_ALO + tid*RSA + q8*4+0] = l;
            tf32_split(v.y, h, l);
            smu[OFF_AHI + tid*RSA + q8*4+1] = h; smu[OFF_ALO + tid*RSA + q8*4+1] = l;
            tf32_split(v.z, h, l);
            smu[OFF_AHI + tid*RSA + q8*4+2] = h; smu[OFF_ALO + tid*RSA + q8*4+2] = l;
            tf32_split(v.w, h, l);
            smu[OFF_AHI + tid*RSA + q8*4+3] = h; smu[OFF_ALO + tid*RSA + q8*4+3] = l;
        }
        {
            uint32_t h, l;
            tf32_split(x[(size_t)row * DD + d], h, l);
            smu[OFF_AHI + tid*RSA + 32] = h;
            smu[OFF_ALO + tid*RSA + 32] = l;
            #pragma unroll
            for (int j = 33; j < 40; j++) {
                smu[OFF_AHI + tid*RSA + j] = 0u;
                smu[OFF_ALO + tid*RSA + j] = 0u;
            }
        }
    }
    __syncthreads();

    const int r0 = lane >> 2, c0 = lane & 3;
    float acc[2][8][4];
    unsigned g0[2] = {0,0}, g1[2] = {0,0}, g2[2] = {0,0};

    // per-thread col pairs (same for all layers): col = n*8 + 2*c0 + {0,1}
    float2 bias2[8];

    // ================= forward layer 0 =================
    mma_round<5, RSW0>(smu, OFF_W0H, OFF_W0L, lane, wrow, acc);
    #pragma unroll
    for (int n = 0; n < 8; n++) bias2[n] = *(const float2*)&sm[MF_B0 + n*8 + 2*c0];
    #pragma unroll
    for (int m = 0; m < 2; m++)
        #pragma unroll
        for (int n = 0; n < 8; n++)
            #pragma unroll
            for (int q = 0; q < 4; q++) {
                int row = wrow + m*16 + r0 + ((q >> 1) << 3);
                int col = n*8 + 2*c0 + (q & 1);
                float z = acc[m][n][q] + ((q & 1) ? bias2[n].y : bias2[n].x);
                unsigned g = (z >= 0.f);
                g0[m] |= g << (n*4 + q);
                float a = g ? z : z * SLOPE;
                uint32_t h, l;
                tf32_split(a, h, l);
                smu[OFF_AHI + row*RSA + col] = h;
                smu[OFF_ALO + row*RSA + col] = l;
            }
    __syncwarp();

    // ================= forward layer 1 =================
    mma_round<8, RSW>(smu, OFF_W1H, OFF_W1L, lane, wrow, acc);
    #pragma unroll
    for (int n = 0; n < 8; n++) bias2[n] = *(const float2*)&sm[MF_B1 + n*8 + 2*c0];
    #pragma unroll
    for (int m = 0; m < 2; m++)
        #pragma unroll
        for (int n = 0; n < 8; n++)
            #pragma unroll
            for (int q = 0; q < 4; q++) {
                int row = wrow + m*16 + r0 + ((q >> 1) << 3);
                int col = n*8 + 2*c0 + (q & 1);
                float z = acc[m][n][q] + ((q & 1) ? bias2[n].y : bias2[n].x);
                unsigned g = (z >= 0.f);
                g1[m] |= g << (n*4 + q);
                float a = g ? z : z * SLOPE;
                uint32_t h, l;
                tf32_split(a, h, l);
                smu[OFF_AHI + row*RSA + col] = h;
                smu[OFF_ALO + row*RSA + col] = l;
            }
    __syncwarp();

    // ================= forward layer 2 + residual head =================
    mma_round<8, RSW>(smu, OFF_W2H, OFF_W2L, lane, wrow, acc);
    #pragma unroll
    for (int n = 0; n < 8; n++) bias2[n] = *(const float2*)&sm[MF_B2 + n*8 + 2*c0];
    float2 wo2[8];
    #pragma unroll
    for (int n = 0; n < 8; n++) wo2[n] = *(const float2*)&sm[MF_WO + n*8 + 2*c0];
    {
        float p[4] = {0.f, 0.f, 0.f, 0.f};
        #pragma unroll
        for (int m = 0; m < 2; m++)
            #pragma unroll
            for (int n = 0; n < 8; n++)
                #pragma unroll
                for (int q = 0; q < 4; q++) {
                    float z = acc[m][n][q] + ((q & 1) ? bias2[n].y : bias2[n].x);
                    unsigned g = (z >= 0.f);
                    g2[m] |= g << (n*4 + q);
                    float a = g ? z : z * SLOPE;
                    p[m*2 + (q >> 1)] += a * ((q & 1) ? wo2[n].y : wo2[n].x);
                }
        #pragma unroll
        for (int i = 0; i < 4; i++) {
            p[i] += __shfl_xor_sync(0xffffffffu, p[i], 1);
            p[i] += __shfl_xor_sync(0xffffffffu, p[i], 2);
        }
        if (c0 == 0) {
            float bb = sm[MF_BO];
            #pragma unroll
            for (int m = 0; m < 2; m++)
                #pragma unroll
                for (int rh = 0; rh < 2; rh++) {
                    int row = wrow + m*16 + r0 + rh*8;
                    out_res[(size_t)(n0 + row) * DD + d] = bb + p[m*2 + rh];
                }
        }
    }

    // ================= tangent seed: t0 = g0 * W0[:,E] =================
    {
        float2 e2[8];
        #pragma unroll
        for (int n = 0; n < 8; n++) e2[n] = *(const float2*)&sm[MF_W0E + n*8 + 2*c0];
        #pragma unroll
        for (int m = 0; m < 2; m++)
            #pragma unroll
            for (int n = 0; n < 8; n++)
                #pragma unroll
                for (int q = 0; q < 4; q++) {
                    int row = wrow + m*16 + r0 + ((q >> 1) << 3);
                    int col = n*8 + 2*c0 + (q & 1);
                    float w = (q & 1) ? e2[n].y : e2[n].x;
                    float t = (((g0[m] >> (n*4 + q)) & 1u) ? 1.f : SLOPE) * w;
                    uint32_t h, l;
                    tf32_split(t, h, l);
                    smu[OFF_AHI + row*RSA + col] = h;
                    smu[OFF_ALO + row*RSA + col] = l;
                }
    }
    __syncwarp();

    // ================= tangent layer 1: t1 = g1*(W1 @ t0) =================
    mma_round<8, RSW>(smu, OFF_W1H, OFF_W1L, lane, wrow, acc);
    #pragma unroll
    for (int m = 0; m < 2; m++)
        #pragma unroll
        for (int n = 0; n < 8; n++)
            #pragma unroll
            for (int q = 0; q < 4; q++) {
                int row = wrow + m*16 + r0 + ((q >> 1) << 3);
                int col = n*8 + 2*c0 + (q & 1);
                float t = (((g1[m] >> (n*4 + q)) & 1u) ? 1.f : SLOPE) * acc[m][n][q];
                uint32_t h, l;
                tf32_split(t, h, l);
                smu[OFF_AHI + row*RSA + col] = h;
                smu[OFF_ALO + row*RSA + col] = l;
            }
    __syncwarp();

    // ================= tangent layer 2 + Jacobian head =================
    mma_round<8, RSW>(smu, OFF_W2H, OFF_W2L, lane, wrow, acc);
    {
        float p[4] = {0.f, 0.f, 0.f, 0.f};
        #pragma unroll
        for (int m = 0; m < 2; m++)
            #pragma unroll
            for (int n = 0; n < 8; n++)
                #pragma unroll
                for (int q = 0; q < 4; q++) {
                    float t = (((g2[m] >> (n*4 + q)) & 1u) ? 1.f : SLOPE) * acc[m][n][q];
                    p[m*2 + (q >> 1)] += t * ((q & 1) ? wo2[n].y : wo2[n].x);
                }
        #pragma unroll
        for (int i = 0; i < 4; i++) {
            p[i] += __shfl_xor_sync(0xffffffffu, p[i], 1);
            p[i] += __shfl_xor_sync(0xffffffffu, p[i], 2);
        }
        if (c0 == 0) {
            #pragma unroll
            for (int m = 0; m < 2; m++)
                #pragma unroll
                for (int rh = 0; rh < 2; rh++) {
                    int row = wrow + m*16 + r0 + rh*8;
                    g_logscratch[(size_t)(n0 + row) * DD + d] = logf(fabsf(p[m*2 + rh]));
                }
        }
    }
}

// deterministic fixed-order reduction over d for log|det J|
__global__ void logdet_reduce_kernel(float* __restrict__ out_log)
{
    int n = blockIdx.x * 256 + threadIdx.x;
    if (n >= NN) return;
    const float4* p = reinterpret_cast<const float4*>(&g_logscratch[(size_t)n * DD]);
    float s = 0.f;
    #pragma unroll
    for (int i = 0; i < DD / 4; i++) {
        float4 v4 = p[i];
        s += v4.x; s += v4.y; s += v4.z; s += v4.w;
    }
    out_log[n] = s;
}

extern "C" void kernel_launch(void* const* d_in, const int* in_sizes, int n_in,
                              void* d_out, int out_size)
{
    const float* x   = (const float*)d_in[0];
    const float* emb = (const float*)d_in[1];
    const float* W0  = (const float*)d_in[2];
    const float* b0  = (const float*)d_in[3];
    const float* W1  = (const float*)d_in[4];
    const float* b1  = (const float*)d_in[5];
    const float* W2  = (const float*)d_in[6];
    const float* b2  = (const float*)d_in[7];
    const float* Wo  = (const float*)d_in[8];
    const float* bo  = (const float*)d_in[9];

    float* out_res = (float*)d_out;            // [N, D]
    float* out_log = (float*)d_out + NN * DD;  // [N]

    cudaFuncSetAttribute(mlp_hmma_kernel,
                         cudaFuncAttributeMaxDynamicSharedMemorySize, SMEM_BYTES);

    dim3 grid(NN / MTILE, DD);   // 250 x 16
    mlp_hmma_kernel<<<grid, TPB, SMEM_BYTES>>>(x, emb, W0, b0, W1, b1, W2, b2, Wo, bo, out_res);
    logdet_reduce_kernel<<<(NN + 255) / 256, 256>>>(out_log);
}

// round 15
// speedup vs baseline: 2.6935x; 1.3193x over previous
#include <cuda_runtime.h>
#include <math.h>
#include <stdint.h>

#define SLOPE 0.2f
#define NB   32
#define TT   1002
#define DD   16
#define EE   32
#define HH   64
#define LEN  1000
#define NN   (NB*LEN)
#define TPB  256
#define MTILE 256

#define RSA   68      // A row stride (floats): 68 % 32 == 4 -> conflict-free frags
#define RSW   68      // W1/W2 row stride
#define RSW0  44      // W0 row stride: 44 % 32 == 12 -> conflict-free

// ---- smem float offsets ----
#define OFF_AHI  0                    // 256*68 = 17408
#define OFF_ALO  17408
#define OFF_W0H  34816                // 64*44 = 2816
#define OFF_W0L  37632
#define OFF_W1H  40448                // 64*68 = 4352
#define OFF_W1L  44800
#define OFF_W2H  49152
#define OFF_W2L  53504
#define MF_B0    57856
#define MF_B1    57920
#define MF_B2    57984
#define MF_WO    58048
#define SMEM_FLOATS 58112
#define SMEM_BYTES  (SMEM_FLOATS * 4)   // 232448 = exactly the 227KB opt-in cap

__device__ float g_logscratch[NN * DD];

static __device__ __forceinline__ void tf32_split(float x, uint32_t& hi, uint32_t& lo) {
    uint32_t h;
    asm("cvt.rna.tf32.f32 %0, %1;" : "=r"(h) : "f"(x));
    float rem = x - __uint_as_float(h);
    uint32_t l;
    asm("cvt.rna.tf32.f32 %0, %1;" : "=r"(l) : "f"(rem));
    hi = h; lo = l;
}

// D += A(16x8) * B(8x8), tf32 inputs, f32 accumulate
static __device__ __forceinline__ void mma8(float c[4], const uint32_t a[4], const uint32_t b[2]) {
    asm volatile(
        "mma.sync.aligned.m16n8k8.row.col.f32.tf32.tf32.f32 "
        "{%0,%1,%2,%3},{%4,%5,%6,%7},{%8,%9},{%0,%1,%2,%3};"
        : "+f"(c[0]), "+f"(c[1]), "+f"(c[2]), "+f"(c[3])
        : "r"(a[0]), "r"(a[1]), "r"(a[2]), "r"(a[3]), "r"(b[0]), "r"(b[1]));
}

// one 3xTF32 GEMM round: acc[2][8][4] += A[warp rows x 8*NK] * W^T
template<int NK, int RSWB>
static __device__ __forceinline__ void mma_round(
    const uint32_t* __restrict__ smu, int bh_off, int bl_off,
    int lane, int wrow, float acc[2][8][4])
{
    #pragma unroll
    for (int m = 0; m < 2; m++)
        #pragma unroll
        for (int n = 0; n < 8; n++)
            #pragma unroll
            for (int q = 0; q < 4; q++) acc[m][n][q] = 0.f;

    const int r0 = lane >> 2, c0 = lane & 3;
    #pragma unroll 2
    for (int k = 0; k < NK; k++) {
        uint32_t ah[2][4], al[2][4];
        #pragma unroll
        for (int m = 0; m < 2; m++)
            #pragma unroll
            for (int q = 0; q < 4; q++) {
                int idx = (wrow + m*16 + r0 + ((q & 1) << 3)) * RSA
                        + k*8 + c0 + ((q >> 1) << 2);
                ah[m][q] = smu[OFF_AHI + idx];
                al[m][q] = smu[OFF_ALO + idx];
            }
        uint32_t bh[8][2], bl[8][2];
        #pragma unroll
        for (int n = 0; n < 8; n++) {
            int idx = (n*8 + r0) * RSWB + k*8 + c0;
            bh[n][0] = smu[bh_off + idx];
            bh[n][1] = smu[bh_off + idx + 4];
            bl[n][0] = smu[bl_off + idx];
            bl[n][1] = smu[bl_off + idx + 4];
        }
        #pragma unroll
        for (int n = 0; n < 8; n++)
            #pragma unroll
            for (int m = 0; m < 2; m++) mma8(acc[m][n], ah[m], bh[n]);
        #pragma unroll
        for (int n = 0; n < 8; n++)
            #pragma unroll
            for (int m = 0; m < 2; m++) mma8(acc[m][n], ah[m], bl[n]);
        #pragma unroll
        for (int n = 0; n < 8; n++)
            #pragma unroll
            for (int m = 0; m < 2; m++) mma8(acc[m][n], al[m], bh[n]);
    }
}

__global__ __launch_bounds__(TPB)
void mlp_hmma_kernel(
    const float* __restrict__ x,   const float* __restrict__ emb,
    const float* __restrict__ W0,  const float* __restrict__ b0,
    const float* __restrict__ W1,  const float* __restrict__ b1,
    const float* __restrict__ W2,  const float* __restrict__ b2,
    const float* __restrict__ Wo,  const float* __restrict__ bo,
    float* __restrict__ out_res)
{
    extern __shared__ __align__(16) float sm[];
    uint32_t* smu = (uint32_t*)sm;

    const int d    = blockIdx.y;
    const int tid  = threadIdx.x;
    const int lane = tid & 31;
    const int wid  = tid >> 5;
    const int n0   = blockIdx.x * MTILE;
    const int wrow = wid * 32;

    // ================= staging =================
    {
        const float* w0g = W0 + (size_t)d * HH * (EE + 1);
        const float* w1g = W1 + (size_t)d * HH * HH;
        const float* w2g = W2 + (size_t)d * HH * HH;
        for (int idx = tid; idx < HH * HH; idx += TPB) {
            int o = idx >> 6, j = idx & 63;
            uint32_t h, l;
            tf32_split(w1g[idx], h, l);
            smu[OFF_W1H + o*RSW + j] = h;
            smu[OFF_W1L + o*RSW + j] = l;
            tf32_split(w2g[idx], h, l);
            smu[OFF_W2H + o*RSW + j] = h;
            smu[OFF_W2L + o*RSW + j] = l;
        }
        for (int idx = tid; idx < HH * 33; idx += TPB) {
            int o = idx / 33, j = idx - o * 33;
            uint32_t h, l;
            tf32_split(w0g[o * 33 + j], h, l);
            smu[OFF_W0H + o*RSW0 + j] = h;
            smu[OFF_W0L + o*RSW0 + j] = l;
        }
        for (int idx = tid; idx < HH * 11; idx += TPB) {   // zero W0 cols 33..43
            int o = idx / 11, j = 33 + idx - o * 11;
            smu[OFF_W0H + o*RSW0 + j] = 0u;
            smu[OFF_W0L + o*RSW0 + j] = 0u;
        }
        if (tid < HH) {
            sm[MF_B0 + tid] = b0[d * HH + tid];
            sm[MF_B1 + tid] = b1[d * HH + tid];
            sm[MF_B2 + tid] = b2[d * HH + tid];
            sm[MF_WO + tid] = Wo[d * HH + tid];
        }

        // inputs: row=tid; cols 0..31 = emb(tf32 split), col 32 = x_t, 33..39 = 0
        int n = n0 + tid, bb = n / LEN;
        int row = bb * TT + (n - bb * LEN) + 2;        // LAGS = 2
        const float4* ev = (const float4*)(emb + (size_t)row * EE);
        #pragma unroll
        for (int q8 = 0; q8 < 8; q8++) {
            float4 v = ev[q8];
            uint32_t h, l;
            tf32_split(v.x, h, l);
            smu[OFF_AHI + tid*RSA + q8*4+0] = h; smu[OFF_ALO + tid*RSA + q8*4+0] = l;
            tf32_split(v.y, h, l);
            smu[OFF_AHI + tid*RSA + q8*4+1] = h; smu[OFF_ALO + tid*RSA + q8*4+1] = l;
            tf32_split(v.z, h, l);
            smu[OFF_AHI + tid*RSA + q8*4+2] = h; smu[OFF_ALO + tid*RSA + q8*4+2] = l;
            tf32_split(v.w, h, l);
            smu[OFF_AHI + tid*RSA + q8*4+3] = h; smu[OFF_ALO + tid*RSA + q8*4+3] = l;
        }
        {
            uint32_t h, l;
            tf32_split(x[(size_t)row * DD + d], h, l);
            smu[OFF_AHI + tid*RSA + 32] = h;
            smu[OFF_ALO + tid*RSA + 32] = l;
            #pragma unroll
            for (int j = 33; j < 40; j++) {
                smu[OFF_AHI + tid*RSA + j] = 0u;
                smu[OFF_ALO + tid*RSA + j] = 0u;
            }
        }
    }
    __syncthreads();

    const int r0 = lane >> 2, c0 = lane & 3;
    float acc[2][8][4];
    unsigned g0[2] = {0,0}, g1[2] = {0,0}, g2[2] = {0,0};
    float2 bias2[8];

    // ================= forward layer 0 =================
    mma_round<5, RSW0>(smu, OFF_W0H, OFF_W0L, lane, wrow, acc);
    #pragma unroll
    for (int n = 0; n < 8; n++) bias2[n] = *(const float2*)&sm[MF_B0 + n*8 + 2*c0];
    #pragma unroll
    for (int m = 0; m < 2; m++)
        #pragma unroll
        for (int n = 0; n < 8; n++)
            #pragma unroll
            for (int q = 0; q < 4; q++) {
                int row = wrow + m*16 + r0 + ((q >> 1) << 3);
                int col = n*8 + 2*c0 + (q & 1);
                float z = acc[m][n][q] + ((q & 1) ? bias2[n].y : bias2[n].x);
                unsigned g = (z >= 0.f);
                g0[m] |= g << (n*4 + q);
                float a = g ? z : z * SLOPE;
                uint32_t h, l;
                tf32_split(a, h, l);
                smu[OFF_AHI + row*RSA + col] = h;
                smu[OFF_ALO + row*RSA + col] = l;
            }
    __syncwarp();

    // ================= forward layer 1 =================
    mma_round<8, RSW>(smu, OFF_W1H, OFF_W1L, lane, wrow, acc);
    #pragma unroll
    for (int n = 0; n < 8; n++) bias2[n] = *(const float2*)&sm[MF_B1 + n*8 + 2*c0];
    #pragma unroll
    for (int m = 0; m < 2; m++)
        #pragma unroll
        for (int n = 0; n < 8; n++)
            #pragma unroll
            for (int q = 0; q < 4; q++) {
                int row = wrow + m*16 + r0 + ((q >> 1) << 3);
                int col = n*8 + 2*c0 + (q & 1);
                float z = acc[m][n][q] + ((q & 1) ? bias2[n].y : bias2[n].x);
                unsigned g = (z >= 0.f);
                g1[m] |= g << (n*4 + q);
                float a = g ? z : z * SLOPE;
                uint32_t h, l;
                tf32_split(a, h, l);
                smu[OFF_AHI + row*RSA + col] = h;
                smu[OFF_ALO + row*RSA + col] = l;
            }
    __syncwarp();

    // ================= forward layer 2 + residual head =================
    mma_round<8, RSW>(smu, OFF_W2H, OFF_W2L, lane, wrow, acc);
    #pragma unroll
    for (int n = 0; n < 8; n++) bias2[n] = *(const float2*)&sm[MF_B2 + n*8 + 2*c0];
    float2 wo2[8];
    #pragma unroll
    for (int n = 0; n < 8; n++) wo2[n] = *(const float2*)&sm[MF_WO + n*8 + 2*c0];
    {
        float p[4] = {0.f, 0.f, 0.f, 0.f};
        #pragma unroll
        for (int m = 0; m < 2; m++)
            #pragma unroll
            for (int n = 0; n < 8; n++)
                #pragma unroll
                for (int q = 0; q < 4; q++) {
                    float z = acc[m][n][q] + ((q & 1) ? bias2[n].y : bias2[n].x);
                    unsigned g = (z >= 0.f);
                    g2[m] |= g << (n*4 + q);
                    float a = g ? z : z * SLOPE;
                    p[m*2 + (q >> 1)] += a * ((q & 1) ? wo2[n].y : wo2[n].x);
                }
        #pragma unroll
        for (int i = 0; i < 4; i++) {
            p[i] += __shfl_xor_sync(0xffffffffu, p[i], 1);
            p[i] += __shfl_xor_sync(0xffffffffu, p[i], 2);
        }
        if (c0 == 0) {
            float bb = bo[d];
            #pragma unroll
            for (int m = 0; m < 2; m++)
                #pragma unroll
                for (int rh = 0; rh < 2; rh++) {
                    int row = wrow + m*16 + r0 + rh*8;
                    out_res[(size_t)(n0 + row) * DD + d] = bb + p[m*2 + rh];
                }
        }
    }

    // ================= tangent seed: t0 = g0 * W0[:,E] =================
    // W0E reconstructed from staged tf32 hi+lo (error ~2^-22, negligible)
    {
        #pragma unroll
        for (int m = 0; m < 2; m++)
            #pragma unroll
            for (int n = 0; n < 8; n++)
                #pragma unroll
                for (int q = 0; q < 4; q++) {
                    int row = wrow + m*16 + r0 + ((q >> 1) << 3);
                    int col = n*8 + 2*c0 + (q & 1);
                    float w = __uint_as_float(smu[OFF_W0H + col*RSW0 + 32])
                            + __uint_as_float(smu[OFF_W0L + col*RSW0 + 32]);
                    float t = (((g0[m] >> (n*4 + q)) & 1u) ? 1.f : SLOPE) * w;
                    uint32_t h, l;
                    tf32_split(t, h, l);
                    smu[OFF_AHI + row*RSA + col] = h;
                    smu[OFF_ALO + row*RSA + col] = l;
                }
    }
    __syncwarp();

    // ================= tangent layer 1: t1 = g1*(W1 @ t0) =================
    mma_round<8, RSW>(smu, OFF_W1H, OFF_W1L, lane, wrow, acc);
    #pragma unroll
    for (int m = 0; m < 2; m++)
        #pragma unroll
        for (int n = 0; n < 8; n++)
            #pragma unroll
            for (int q = 0; q < 4; q++) {
                int row = wrow + m*16 + r0 + ((q >> 1) << 3);
                int col = n*8 + 2*c0 + (q & 1);
                float t = (((g1[m] >> (n*4 + q)) & 1u) ? 1.f : SLOPE) * acc[m][n][q];
                uint32_t h, l;
                tf32_split(t, h, l);
                smu[OFF_AHI + row*RSA + col] = h;
                smu[OFF_ALO + row*RSA + col] = l;
            }
    __syncwarp();

    // ================= tangent layer 2 + Jacobian head =================
    mma_round<8, RSW>(smu, OFF_W2H, OFF_W2L, lane, wrow, acc);
    {
        float p[4] = {0.f, 0.f, 0.f, 0.f};
        #pragma unroll
        for (int m = 0; m < 2; m++)
            #pragma unroll
            for (int n = 0; n < 8; n++)
                #pragma unroll
                for (int q = 0; q < 4; q++) {
                    float t = (((g2[m] >> (n*4 + q)) & 1u) ? 1.f : SLOPE) * acc[m][n][q];
                    p[m*2 + (q >> 1)] += t * ((q & 1) ? wo2[n].y : wo2[n].x);
                }
        #pragma unroll
        for (int i = 0; i < 4; i++) {
            p[i] += __shfl_xor_sync(0xffffffffu, p[i], 1);
            p[i] += __shfl_xor_sync(0xffffffffu, p[i], 2);
        }
        if (c0 == 0) {
            #pragma unroll
            for (int m = 0; m < 2; m++)
                #pragma unroll
                for (int rh = 0; rh < 2; rh++) {
                    int row = wrow + m*16 + r0 + rh*8;
                    g_logscratch[(size_t)(n0 + row) * DD + d] = logf(fabsf(p[m*2 + rh]));
                }
        }
    }
}

// deterministic fixed-order reduction over d for log|det J|
__global__ void logdet_reduce_kernel(float* __restrict__ out_log)
{
    int n = blockIdx.x * 256 + threadIdx.x;
    if (n >= NN) return;
    const float4* p = reinterpret_cast<const float4*>(&g_logscratch[(size_t)n * DD]);
    float s = 0.f;
    #pragma unroll
    for (int i = 0; i < DD / 4; i++) {
        float4 v4 = p[i];
        s += v4.x; s += v4.y; s += v4.z; s += v4.w;
    }
    out_log[n] = s;
}

extern "C" void kernel_launch(void* const* d_in, const int* in_sizes, int n_in,
                              void* d_out, int out_size)
{
    const float* x   = (const float*)d_in[0];
    const float* emb = (const float*)d_in[1];
    const float* W0  = (const float*)d_in[2];
    const float* b0  = (const float*)d_in[3];
    const float* W1  = (const float*)d_in[4];
    const float* b1  = (const float*)d_in[5];
    const float* W2  = (const float*)d_in[6];
    const float* b2  = (const float*)d_in[7];
    const float* Wo  = (const float*)d_in[8];
    const float* bo  = (const float*)d_in[9];

    float* out_res = (float*)d_out;            // [N, D]
    float* out_log = (float*)d_out + NN * DD;  // [N]

    cudaFuncSetAttribute(mlp_hmma_kernel,
                         cudaFuncAttributeMaxDynamicSharedMemorySize, SMEM_BYTES);

    dim3 grid(NN / MTILE, DD);   // 125 x 16
    mlp_hmma_kernel<<<grid, TPB, SMEM_BYTES>>>(x, emb, W0, b0, W1, b1, W2, b2, Wo, bo, out_res);
    logdet_reduce_kernel<<<(NN + 255) / 256, 256>>>(out_log);
}